// round 15
// baseline (speedup 1.0000x reference)
#include <cuda_runtime.h>
#include <cuda_fp16.h>
#include <math.h>
#include <stdint.h>

#define Bb   4
#define SS   1024
#define DD   1024
#define HH   16
#define HKK  8
#define HDD  64
#define FFF  3072
#define LL   4
#define NTOK (Bb*SS)
#define WIN_ 12
#define QKVW 2048

// ---------------- scratch (device globals; no allocations allowed) -----------
__device__ float g_h  [(size_t)NTOK*DD];
__device__ float g_qkv[(size_t)NTOK*QKVW];
// fp16 activation planes
__device__ __half g_nh[(size_t)NTOK*DD];
__device__ __half g_ch[(size_t)NTOK*DD];
__device__ __half g_ah[(size_t)NTOK*FFF];
// fp16 attention operand planes
__device__ __half g_qh[(size_t)Bb*HH*SS*HDD];
__device__ __half g_kh[(size_t)Bb*HKK*SS*HDD];
__device__ __half g_vh[(size_t)Bb*HKK*SS*HDD];

// fp16 weights transposed to [N][K]; per-layer element offsets:
#define W1_QKV   0
#define W1_WO    2097152
#define W1_GU    3145728
#define W1_DN    9437184
#define W1_LAYER 12582912
__device__ __half g_wt[(size_t)LL*W1_LAYER];

// ---------------- helpers -----------------------------------------------------
__device__ __forceinline__ uint32_t smem_u32(const void* p){
    uint32_t a;
    asm("{ .reg .u64 t; cvta.to.shared.u64 t, %1; cvt.u32.u64 %0, t; }" : "=r"(a) : "l"(p));
    return a;
}
__device__ __forceinline__ uint32_t packh(__half a, __half b){
    __half2 t(a, b);
    return *(uint32_t*)&t;
}
__device__ __forceinline__ uint32_t f22h(float a, float b){
    __half2 t = __floats2half2_rn(a, b);
    return *(uint32_t*)&t;
}
__device__ __forceinline__ uint2 pack4h(float4 v){
    return make_uint2(packh(__float2half_rn(v.x), __float2half_rn(v.y)),
                      packh(__float2half_rn(v.z), __float2half_rn(v.w)));
}

#define LDSM4(r, addr) \
    asm volatile("ldmatrix.sync.aligned.m8n8.x4.shared.b16 {%0,%1,%2,%3}, [%4];" \
        : "=r"((r)[0]), "=r"((r)[1]), "=r"((r)[2]), "=r"((r)[3]) : "r"(addr))

#define LDSM4T(r, addr) \
    asm volatile("ldmatrix.sync.aligned.m8n8.x4.trans.shared.b16 {%0,%1,%2,%3}, [%4];" \
        : "=r"((r)[0]), "=r"((r)[1]), "=r"((r)[2]), "=r"((r)[3]) : "r"(addr))

#define MMA16816(c, a, b0, b1) \
    asm volatile("mma.sync.aligned.m16n8k16.row.col.f32.f16.f16.f32 " \
        "{%0,%1,%2,%3}, {%4,%5,%6,%7}, {%8,%9}, {%0,%1,%2,%3};" \
        : "+f"((c)[0]), "+f"((c)[1]), "+f"((c)[2]), "+f"((c)[3]) \
        : "r"((a)[0]), "r"((a)[1]), "r"((a)[2]), "r"((a)[3]), "r"(b0), "r"(b1))

#define CPASYNC16(dst, src) \
    asm volatile("cp.async.cg.shared.global [%0], [%1], 16;" \
        :: "r"(dst), "l"((unsigned long long)__cvta_generic_to_global(src)))

// ============ GEMM: C[M,N] (+)= A[M,K] * Bt[N,K]^T, fp16 in / fp32 acc =======
// CTA tile 128x128, BK=32/stage, 2 stages, 256 threads (8 warps = 4m x 2n).
// FS=1: interleaved gate/up columns; epilogue computes silu(gate)*up -> fp16 Ch.
template<int ACC, int FS>
__global__ void __launch_bounds__(256, 2) gemm_mma(
        const __half* __restrict__ A, const __half* __restrict__ Bt,
        float* __restrict__ C, __half* __restrict__ Ch, int K, int N){
    __shared__ __align__(16) __half smg[2*8192];
    const int tid = threadIdx.x, lane = tid & 31, wid = tid >> 5;
    const int wm = (wid >> 1) << 5, wn = (wid & 1) << 6;
    const int bm = blockIdx.y << 7, bn = blockIdx.x << 7;
    const uint32_t sb = smem_u32(smg);

    float c[2][8][4];
    #pragma unroll
    for(int i = 0; i < 2; i++)
        #pragma unroll
        for(int j = 0; j < 8; j++){
            c[i][j][0] = 0.f; c[i][j][1] = 0.f; c[i][j][2] = 0.f; c[i][j][3] = 0.f;
        }

    const int cid0 = tid << 1;
    auto prefetch = [&](int s, int kt){
        #pragma unroll
        for(int rg = 0; rg < 2; rg++){
            #pragma unroll
            for(int j = 0; j < 2; j++){
                int cid = cid0 | j;
                int row = cid >> 2, ch = cid & 3;
                const __half* src = (rg ? Bt : A) +
                    (size_t)((rg ? bn : bm) + row) * K + kt * 32 + (ch << 3);
                uint32_t dst = sb + 2u * (uint32_t)(s * 8192 + rg * 4096 +
                               row * 32 + ((ch ^ ((row >> 1) & 3)) << 3));
                CPASYNC16(dst, src);
            }
        }
    };

    const int T = K >> 5;
    prefetch(0, 0);
    asm volatile("cp.async.commit_group;");

    for(int kt = 0; kt < T; kt++){
        const int s = kt & 1;
        if(kt + 1 < T){
            prefetch(s ^ 1, kt + 1);
            asm volatile("cp.async.commit_group;");
            asm volatile("cp.async.wait_group 1;");
        } else {
            asm volatile("cp.async.wait_group 0;");
        }
        __syncthreads();

        const uint32_t stg = sb + 2u * (uint32_t)(s * 8192);
        #pragma unroll
        for(int kk = 0; kk < 2; kk++){
            uint32_t a[2][4];
            #pragma unroll
            for(int mt = 0; mt < 2; mt++){
                int R = wm + mt * 16 + (lane & 15);
                int phys = (kk * 2 + (lane >> 4)) ^ ((R >> 1) & 3);
                LDSM4(a[mt], stg + 2u * (uint32_t)(R * 32 + (phys << 3)));
            }
            #pragma unroll
            for(int ng = 0; ng < 4; ng++){
                int R = wn + ng * 16 + (lane & 7) + ((lane >> 4) << 3);
                int phys = (kk * 2 + ((lane >> 3) & 1)) ^ ((R >> 1) & 3);
                uint32_t b[4];
                LDSM4(b, stg + 2u * (uint32_t)(4096 + R * 32 + (phys << 3)));
                #pragma unroll
                for(int mt = 0; mt < 2; mt++){
                    MMA16816(c[mt][2*ng],   a[mt], b[0], b[1]);
                    MMA16816(c[mt][2*ng+1], a[mt], b[2], b[3]);
                }
            }
        }
        __syncthreads();
    }

    // ---- epilogue ----
    #pragma unroll
    for(int mt = 0; mt < 2; mt++)
        #pragma unroll
        for(int nt = 0; nt < 8; nt++){
            int r  = bm + wm + mt * 16 + (lane >> 2);
            int cc = bn + wn + nt * 8 + ((lane & 3) << 1);
            if(FS){
                // cc even = gate_j, cc+1 = up_j, j = cc>>1
                int j = cc >> 1;
                float g0 = c[mt][nt][0], u0 = c[mt][nt][1];
                float g1 = c[mt][nt][2], u1 = c[mt][nt][3];
                float o0 = g0 / (1.f + expf(-g0)) * u0;
                float o1 = g1 / (1.f + expf(-g1)) * u1;
                Ch[(size_t)r * (N >> 1) + j]       = __float2half_rn(o0);
                Ch[(size_t)(r + 8) * (N >> 1) + j] = __float2half_rn(o1);
            } else {
                float* p0 = C + (size_t)r * N + cc;
                float* p1 = C + (size_t)(r + 8) * N + cc;
                float2 v0 = make_float2(c[mt][nt][0], c[mt][nt][1]);
                float2 v1 = make_float2(c[mt][nt][2], c[mt][nt][3]);
                if(ACC){
                    float2 o = *(const float2*)p0; v0.x += o.x; v0.y += o.y;
                    o = *(const float2*)p1;        v1.x += o.x; v1.y += o.y;
                }
                *(float2*)p0 = v0;
                *(float2*)p1 = v1;
            }
        }
}

// ---------------- transpose + fp16 convert: d[n*nmul+noff][k] = src[k][n] ----
__global__ void transpose_fp16(const float* __restrict__ src,
                               __half* __restrict__ dst, int K, int N,
                               int nmul, int noff){
    __shared__ float t[32][33];
    int k0 = blockIdx.y << 5, n0 = blockIdx.x << 5;
    int x = threadIdx.x, y = threadIdx.y;
    #pragma unroll
    for(int i = 0; i < 32; i += 8) t[y + i][x] = src[(size_t)(k0 + y + i) * N + n0 + x];
    __syncthreads();
    #pragma unroll
    for(int i = 0; i < 32; i += 8)
        dst[((size_t)(n0 + y + i) * nmul + noff) * K + k0 + x] = __float2half_rn(t[x][y + i]);
}

// ---------------- RMSNorm over rows of width DD ------------------------------
template<int HF>
__global__ void rmsnorm_k(const float* __restrict__ x, const float* __restrict__ w,
                          float* __restrict__ out, __half* __restrict__ oh){
    int row = blockIdx.x;
    const float4* xr = (const float4*)(x + (size_t)row * DD);
    float4 v = xr[threadIdx.x];
    float ss = v.x*v.x + v.y*v.y + v.z*v.z + v.w*v.w;
    __shared__ float red[8];
    #pragma unroll
    for(int o = 16; o; o >>= 1) ss += __shfl_xor_sync(~0u, ss, o);
    if((threadIdx.x & 31) == 0) red[threadIdx.x >> 5] = ss;
    __syncthreads();
    if(threadIdx.x < 8){
        float t = red[threadIdx.x];
        #pragma unroll
        for(int o = 4; o; o >>= 1) t += __shfl_xor_sync(0xff, t, o);
        if(threadIdx.x == 0) red[0] = rsqrtf(t / (float)DD + 1e-6f);
    }
    __syncthreads();
    float r = red[0];
    float4 wv = ((const float4*)w)[threadIdx.x];
    float4 o4 = make_float4(v.x*r*wv.x, v.y*r*wv.y, v.z*r*wv.z, v.w*r*wv.w);
    if(HF){
        *(uint2*)&oh[(size_t)row * DD + (threadIdx.x << 2)] = pack4h(o4);
    } else {
        ((float4*)(out + (size_t)row * DD))[threadIdx.x] = o4;
    }
}

// ---------------- QK RMSNorm + RoPE + fp16 plane emission --------------------
// heads 0..15: Q (scaled by 1/8), 16..23: K, 24..31: V (plain convert)
__global__ void qknorm_rope_k(const float* __restrict__ qw, const float* __restrict__ kw){
    int gw   = (blockIdx.x * blockDim.x + threadIdx.x) >> 5;
    int lane = threadIdx.x & 31;
    if(gw >= NTOK * 32) return;
    int token = gw >> 5;
    int head  = gw & 31;
    int b = token >> 10, s = token & (SS - 1);
    const float* src;
    __half* dst;
    if(head < 16){
        src = g_qkv + (size_t)token * QKVW + head * HDD;
        dst = g_qh + (((size_t)b * HH + head) * SS + s) * HDD;
    } else if(head < 24){
        src = g_qkv + (size_t)token * QKVW + 1024 + (head - 16) * HDD;
        dst = g_kh + (((size_t)b * HKK + head - 16) * SS + s) * HDD;
    } else {
        src = g_qkv + (size_t)token * QKVW + 1536 + (head - 24) * HDD;
        dst = g_vh + (((size_t)b * HKK + head - 24) * SS + s) * HDD;
    }
    float x0 = src[lane], x1 = src[lane + 32];
    if(head < 24){
        const float* wn = (head < 16) ? qw : kw;
        float ss2 = x0*x0 + x1*x1;
        #pragma unroll
        for(int o = 16; o; o >>= 1) ss2 += __shfl_xor_sync(~0u, ss2, o);
        float r = rsqrtf(ss2 / (float)HDD + 1e-6f);
        x0 = x0 * r * wn[lane];
        x1 = x1 * r * wn[lane + 32];
        float inv = expf(-(float)lane * 0.431734704963f);   // ln(1e6)/32
        float ang = (float)s * inv;
        float sn, cs; sincosf(ang, &sn, &cs);
        float y0 = x0 * cs - x1 * sn;
        float y1 = x1 * cs + x0 * sn;
        if(head < 16){ y0 *= 0.125f; y1 *= 0.125f; }   // fold softmax scale (exact)
        dst[lane]      = __float2half_rn(y0);
        dst[lane + 32] = __float2half_rn(y1);
    } else {
        dst[lane]      = __float2half_rn(x0);
        dst[lane + 32] = __float2half_rn(x1);
    }
}

// ---------------- tensor-core flash attention --------------------------------
// block: 64 queries x (b,h); 128 threads = 4 warps, 16 q-rows each.
// K/V tiles 64x64 fp16, double-buffered cp.async; fragment online softmax.
__global__ void __launch_bounds__(128) attn_mma(const int* __restrict__ amask,
                                                int win, __half* __restrict__ Ch){
    __shared__ __align__(16) __half Qs[4096];
    __shared__ __align__(16) __half Ks[2][4096];
    __shared__ __align__(16) __half Vs[2][4096];
    __shared__ int msk[64];
    const int b = blockIdx.z, h = blockIdx.y, q0 = blockIdx.x << 6;
    const int kvh = h >> 1;
    const int tid = threadIdx.x, lane = tid & 31, w = tid >> 5;
    const uint32_t sq = smem_u32(Qs);
    const uint32_t sk = smem_u32(Ks);
    const uint32_t sv = smem_u32(Vs);

    const __half* Qg = g_qh + (((size_t)b * HH + h) * SS + q0) * HDD;
    const __half* Kg = g_kh + ((size_t)b * HKK + kvh) * SS * HDD;
    const __half* Vg = g_vh + ((size_t)b * HKK + kvh) * SS * HDD;

    // Q tile (64x64) via cp.async, swizzled rows of 8 chunks
    #pragma unroll
    for(int i = 0; i < 4; i++){
        int cid = tid + (i << 7);
        int row = cid >> 3, ch = cid & 7;
        CPASYNC16(sq + (uint32_t)(row * 128 + ((ch ^ (row & 7)) << 4)),
                  Qg + row * HDD + ch * 8);
    }
    const bool full = (win >= SS);
    int kbeg = 0, kend = SS;
    if(!full){ kbeg = max(0, q0 - win) & ~63; kend = min(SS, q0 + 63 + win + 1); }

    auto ldtile = [&](int s, int kt){
        #pragma unroll
        for(int i = 0; i < 4; i++){
            int cid = tid + (i << 7);
            int row = cid >> 3, ch = cid & 7;
            uint32_t off = (uint32_t)((s << 13) + row * 128 + ((ch ^ (row & 7)) << 4));
            CPASYNC16(sk + off, Kg + (size_t)(kt + row) * HDD + ch * 8);
            CPASYNC16(sv + off, Vg + (size_t)(kt + row) * HDD + ch * 8);
        }
    };
    ldtile(0, kbeg);
    asm volatile("cp.async.commit_group;");

    float o[8][4];
    #pragma unroll
    for(int i = 0; i < 8; i++){ o[i][0]=0.f; o[i][1]=0.f; o[i][2]=0.f; o[i][3]=0.f; }
    float m0 = -1e30f, m1 = -1e30f, l0 = 0.f, l1 = 0.f;
    uint32_t qa[4][4];

    const int nTiles = (kend - kbeg + 63) >> 6;
    for(int it = 0; it < nTiles; it++){
        const int kt = kbeg + (it << 6);
        const int s = it & 1;
        if(it + 1 < nTiles){
            ldtile(s ^ 1, kt + 64);
            asm volatile("cp.async.commit_group;");
            asm volatile("cp.async.wait_group 1;");
        } else {
            asm volatile("cp.async.wait_group 0;");
        }
        if(tid < 64) msk[tid] = amask[b * SS + kt + tid];
        __syncthreads();
        if(it == 0){
            #pragma unroll
            for(int kk = 0; kk < 4; kk++){
                int R = (w << 4) + (lane & 15);
                int ch = (kk << 1) + (lane >> 4);
                LDSM4(qa[kk], sq + (uint32_t)(R * 128 + ((ch ^ (R & 7)) << 4)));
            }
        }
        // ---- scores S = Q K^T (scale pre-folded into Q) ----
        float sc[8][4];
        #pragma unroll
        for(int i = 0; i < 8; i++){ sc[i][0]=0.f; sc[i][1]=0.f; sc[i][2]=0.f; sc[i][3]=0.f; }
        const uint32_t skb = sk + (uint32_t)(s << 13);
        #pragma unroll
        for(int kk = 0; kk < 4; kk++){
            #pragma unroll
            for(int ng = 0; ng < 4; ng++){
                int R = (ng << 4) + (lane & 7) + ((lane >> 4) << 3);
                int ch = (kk << 1) + ((lane >> 3) & 1);
                uint32_t bk[4];
                LDSM4(bk, skb + (uint32_t)(R * 128 + ((ch ^ (R & 7)) << 4)));
                MMA16816(sc[2*ng],   qa[kk], bk[0], bk[1]);
                MMA16816(sc[2*ng+1], qa[kk], bk[2], bk[3]);
            }
        }
        // ---- mask + online softmax ----
        const int qr0 = q0 + (w << 4) + (lane >> 2), qr1 = qr0 + 8;
        float mx0 = -1e30f, mx1 = -1e30f;
        #pragma unroll
        for(int nt = 0; nt < 8; nt++){
            int c0 = (nt << 3) + ((lane & 3) << 1);
            int j0 = kt + c0, j1 = j0 + 1;
            bool k0 = msk[c0] > 0, k1 = msk[c0 + 1] > 0;
            if(!(k0 && (full || abs(qr0 - j0) <= win))) sc[nt][0] = -1e30f;
            if(!(k1 && (full || abs(qr0 - j1) <= win))) sc[nt][1] = -1e30f;
            if(!(k0 && (full || abs(qr1 - j0) <= win))) sc[nt][2] = -1e30f;
            if(!(k1 && (full || abs(qr1 - j1) <= win))) sc[nt][3] = -1e30f;
            mx0 = fmaxf(mx0, fmaxf(sc[nt][0], sc[nt][1]));
            mx1 = fmaxf(mx1, fmaxf(sc[nt][2], sc[nt][3]));
        }
        mx0 = fmaxf(mx0, __shfl_xor_sync(~0u, mx0, 1));
        mx0 = fmaxf(mx0, __shfl_xor_sync(~0u, mx0, 2));
        mx1 = fmaxf(mx1, __shfl_xor_sync(~0u, mx1, 1));
        mx1 = fmaxf(mx1, __shfl_xor_sync(~0u, mx1, 2));
        float mn0 = fmaxf(m0, mx0), mn1 = fmaxf(m1, mx1);
        float cor0 = expf(m0 - mn0), cor1 = expf(m1 - mn1);
        float s0 = 0.f, s1 = 0.f;
        #pragma unroll
        for(int nt = 0; nt < 8; nt++){
            sc[nt][0] = (sc[nt][0] > -1e29f) ? expf(sc[nt][0] - mn0) : 0.f;
            sc[nt][1] = (sc[nt][1] > -1e29f) ? expf(sc[nt][1] - mn0) : 0.f;
            sc[nt][2] = (sc[nt][2] > -1e29f) ? expf(sc[nt][2] - mn1) : 0.f;
            sc[nt][3] = (sc[nt][3] > -1e29f) ? expf(sc[nt][3] - mn1) : 0.f;
            s0 += sc[nt][0] + sc[nt][1];
            s1 += sc[nt][2] + sc[nt][3];
        }
        s0 += __shfl_xor_sync(~0u, s0, 1); s0 += __shfl_xor_sync(~0u, s0, 2);
        s1 += __shfl_xor_sync(~0u, s1, 1); s1 += __shfl_xor_sync(~0u, s1, 2);
        l0 = l0 * cor0 + s0;  l1 = l1 * cor1 + s1;
        m0 = mn0;  m1 = mn1;
        #pragma unroll
        for(int nt = 0; nt < 8; nt++){
            o[nt][0] *= cor0; o[nt][1] *= cor0;
            o[nt][2] *= cor1; o[nt][3] *= cor1;
        }
        // ---- O += P V  (P fp16 from score fragments) ----
        const uint32_t svb = sv + (uint32_t)(s << 13);
        #pragma unroll
        for(int kk = 0; kk < 4; kk++){
            uint32_t pa[4];
            pa[0] = f22h(sc[2*kk][0],   sc[2*kk][1]);
            pa[1] = f22h(sc[2*kk][2],   sc[2*kk][3]);
            pa[2] = f22h(sc[2*kk+1][0], sc[2*kk+1][1]);
            pa[3] = f22h(sc[2*kk+1][2], sc[2*kk+1][3]);
            #pragma unroll
            for(int hg = 0; hg < 4; hg++){
                int R = (kk << 4) + (((lane >> 3) & 1) << 3) + (lane & 7);
                int ch = (hg << 1) + (lane >> 4);
                uint32_t bv[4];
                LDSM4T(bv, svb + (uint32_t)(R * 128 + ((ch ^ (R & 7)) << 4)));
                MMA16816(o[2*hg],   pa, bv[0], bv[1]);
                MMA16816(o[2*hg+1], pa, bv[2], bv[3]);
            }
        }
        __syncthreads();
    }
    // ---- write ctx (fp16, [token][h*64+d] layout for wo GEMM) ----
    float i0 = (l0 > 0.f) ? 1.f / l0 : 0.f;
    float i1 = (l1 > 0.f) ? 1.f / l1 : 0.f;
    const int row0 = (b << 10) + q0 + (w << 4) + (lane >> 2);
    const int row1 = row0 + 8;
    #pragma unroll
    for(int nt = 0; nt < 8; nt++){
        int col = (h << 6) + (nt << 3) + ((lane & 3) << 1);
        *(uint32_t*)&Ch[(size_t)row0 * DD + col] = f22h(o[nt][0] * i0, o[nt][1] * i0);
        *(uint32_t*)&Ch[(size_t)row1 * DD + col] = f22h(o[nt][2] * i1, o[nt][3] * i1);
    }
}

// ---------------- driver -----------------------------------------------------
extern "C" void kernel_launch(void* const* d_in, const int* in_sizes, int n_in,
                              void* d_out, int out_size){
    const float* emb = (const float*)d_in[0];
    const float* wq  = (const float*)d_in[1];
    const float* wk  = (const float*)d_in[2];
    const float* wv  = (const float*)d_in[3];
    const float* wo  = (const float*)d_in[4];
    const float* qnw = (const float*)d_in[5];
    const float* knw = (const float*)d_in[6];
    const float* ln1 = (const float*)d_in[7];
    const float* ln2 = (const float*)d_in[8];
    const float* wg  = (const float*)d_in[9];
    const float* wu  = (const float*)d_in[10];
    const float* wd  = (const float*)d_in[11];
    const float* nw  = (const float*)d_in[12];
    const int*   am  = (const int*)d_in[13];

    float *p_h, *p_qkv;
    __half *p_wt, *p_nh, *p_ch, *p_ah;
    cudaGetSymbolAddress((void**)&p_h,   g_h);
    cudaGetSymbolAddress((void**)&p_qkv, g_qkv);
    cudaGetSymbolAddress((void**)&p_wt,  g_wt);
    cudaGetSymbolAddress((void**)&p_nh,  g_nh);
    cudaGetSymbolAddress((void**)&p_ch,  g_ch);
    cudaGetSymbolAddress((void**)&p_ah,  g_ah);

    cudaMemcpyAsync(p_h, emb, sizeof(float) * (size_t)NTOK * DD,
                    cudaMemcpyDeviceToDevice);

    dim3 tb(32, 8);
    for(int l = 0; l < LL; l++){
        __half* wb = p_wt + (size_t)l * W1_LAYER;
        transpose_fp16<<<dim3(32, 32), tb>>>(wq + (size_t)l*1024*1024,
            wb + W1_QKV,             1024, 1024, 1, 0);
        transpose_fp16<<<dim3(16, 32), tb>>>(wk + (size_t)l*1024*512,
            wb + W1_QKV + 1048576,   1024, 512, 1, 0);
        transpose_fp16<<<dim3(16, 32), tb>>>(wv + (size_t)l*1024*512,
            wb + W1_QKV + 1572864,   1024, 512, 1, 0);
        transpose_fp16<<<dim3(32, 32), tb>>>(wo + (size_t)l*1024*1024,
            wb + W1_WO,              1024, 1024, 1, 0);
        // gate/up interleaved: n' = 2n (gate), 2n+1 (up)
        transpose_fp16<<<dim3(96, 32), tb>>>(wg + (size_t)l*1024*FFF,
            wb + W1_GU,              1024, 3072, 2, 0);
        transpose_fp16<<<dim3(96, 32), tb>>>(wu + (size_t)l*1024*FFF,
            wb + W1_GU,              1024, 3072, 2, 1);
        transpose_fp16<<<dim3(32, 96), tb>>>(wd + (size_t)l*FFF*1024,
            wb + W1_DN,              3072, 1024, 1, 0);
    }

    for(int l = 0; l < LL; l++){
        __half* wb = p_wt + (size_t)l * W1_LAYER;
        rmsnorm_k<1><<<NTOK, 256>>>(p_h, ln1 + (size_t)l * DD, nullptr, p_nh);
        gemm_mma<0,0><<<dim3(16, 32), 256>>>(p_nh, wb + W1_QKV, p_qkv, nullptr,
                                             1024, QKVW);
        qknorm_rope_k<<<NTOK * 32 / 4, 128>>>(qnw + (size_t)l * HDD,
                                              knw + (size_t)l * HDD);
        attn_mma<<<dim3(SS / 64, HH, Bb), 128>>>(am, (l % 2 == 0) ? SS : WIN_, p_ch);
        gemm_mma<1,0><<<dim3(8, 32), 256>>>(p_ch, wb + W1_WO, p_h, nullptr,
                                            1024, 1024);
        rmsnorm_k<1><<<NTOK, 256>>>(p_h, ln2 + (size_t)l * DD, nullptr, p_nh);
        gemm_mma<0,1><<<dim3(48, 32), 256>>>(p_nh, wb + W1_GU, nullptr, p_ah,
                                             1024, 6144);
        gemm_mma<1,0><<<dim3(8, 32), 256>>>(p_ah, wb + W1_DN, p_h, nullptr,
                                            3072, 1024);
    }
    rmsnorm_k<0><<<NTOK, 256>>>(p_h, nw, (float*)d_out, nullptr);
}

// round 16
// speedup vs baseline: 1.6521x; 1.6521x over previous
#include <cuda_runtime.h>
#include <cuda_fp16.h>
#include <math.h>
#include <stdint.h>

#define Bb   4
#define SS   1024
#define DD   1024
#define HH   16
#define HKK  8
#define HDD  64
#define FFF  3072
#define LL   4
#define NTOK (Bb*SS)
#define WIN_ 12

// ---------------- scratch (device globals; no allocations allowed) -----------
__device__ float g_h [(size_t)NTOK*DD];
// fp16 activation planes
__device__ __half g_nh[(size_t)NTOK*DD];
__device__ __half g_ch[(size_t)NTOK*DD];
__device__ __half g_ah[(size_t)NTOK*FFF];
// fp16 attention operand planes
__device__ __half g_qh[(size_t)Bb*HH*SS*HDD];
__device__ __half g_kh[(size_t)Bb*HKK*SS*HDD];
__device__ __half g_vh[(size_t)Bb*HKK*SS*HDD];

// fp16 weights transposed to [N][K]; per-layer element offsets:
#define W1_QKV   0
#define W1_WO    2097152
#define W1_GU    3145728
#define W1_DN    9437184
#define W1_LAYER 12582912
__device__ __half g_wt[(size_t)LL*W1_LAYER];

// ---------------- helpers -----------------------------------------------------
__device__ __forceinline__ uint32_t smem_u32(const void* p){
    uint32_t a;
    asm("{ .reg .u64 t; cvta.to.shared.u64 t, %1; cvt.u32.u64 %0, t; }" : "=r"(a) : "l"(p));
    return a;
}
__device__ __forceinline__ uint32_t packh(__half a, __half b){
    __half2 t(a, b);
    return *(uint32_t*)&t;
}
__device__ __forceinline__ uint32_t f22h(float a, float b){
    __half2 t = __floats2half2_rn(a, b);
    return *(uint32_t*)&t;
}
__device__ __forceinline__ uint2 pack4h(float4 v){
    return make_uint2(packh(__float2half_rn(v.x), __float2half_rn(v.y)),
                      packh(__float2half_rn(v.z), __float2half_rn(v.w)));
}

#define LDSM4(r, addr) \
    asm volatile("ldmatrix.sync.aligned.m8n8.x4.shared.b16 {%0,%1,%2,%3}, [%4];" \
        : "=r"((r)[0]), "=r"((r)[1]), "=r"((r)[2]), "=r"((r)[3]) : "r"(addr))

#define LDSM4T(r, addr) \
    asm volatile("ldmatrix.sync.aligned.m8n8.x4.trans.shared.b16 {%0,%1,%2,%3}, [%4];" \
        : "=r"((r)[0]), "=r"((r)[1]), "=r"((r)[2]), "=r"((r)[3]) : "r"(addr))

#define MMA16816(c, a, b0, b1) \
    asm volatile("mma.sync.aligned.m16n8k16.row.col.f32.f16.f16.f32 " \
        "{%0,%1,%2,%3}, {%4,%5,%6,%7}, {%8,%9}, {%0,%1,%2,%3};" \
        : "+f"((c)[0]), "+f"((c)[1]), "+f"((c)[2]), "+f"((c)[3]) \
        : "r"((a)[0]), "r"((a)[1]), "r"((a)[2]), "r"((a)[3]), "r"(b0), "r"(b1))

#define CPASYNC16(dst, src) \
    asm volatile("cp.async.cg.shared.global [%0], [%1], 16;" \
        :: "r"(dst), "l"((unsigned long long)__cvta_generic_to_global(src)))

// ============ GEMM: C[M,N] (+)= A[M,K] * Bt[N,K]^T, fp16 in / fp32 acc =======
// CTA tile 128x128, BK=32/stage, 3 stages, ONE sync per iter, 256 threads.
// EP=0: fp32 C (+=ACC).  EP=1: interleaved gate/up -> silu(g)*u fp16 Ch.
// EP=2: fused QK-RMSNorm+RoPE epilogue -> q/k/v fp16 planes (qkv projection).
template<int ACC, int EP>
__global__ void __launch_bounds__(256, 2) gemm_mma(
        const __half* __restrict__ A, const __half* __restrict__ Bt,
        float* __restrict__ C, __half* __restrict__ Ch, int K, int N,
        const float* __restrict__ qw, const float* __restrict__ kw,
        __half* __restrict__ qp, __half* __restrict__ kp, __half* __restrict__ vp){
    __shared__ __align__(16) __half smg[3*8192];
    const int tid = threadIdx.x, lane = tid & 31, wid = tid >> 5;
    const int wm = (wid >> 1) << 5, wn = (wid & 1) << 6;
    const int bm = blockIdx.y << 7, bn = blockIdx.x << 7;
    const uint32_t sb = smem_u32(smg);

    float c[2][8][4];
    #pragma unroll
    for(int i = 0; i < 2; i++)
        #pragma unroll
        for(int j = 0; j < 8; j++){
            c[i][j][0] = 0.f; c[i][j][1] = 0.f; c[i][j][2] = 0.f; c[i][j][3] = 0.f;
        }

    const int cid0 = tid << 1;
    auto prefetch = [&](int s, int kt){
        #pragma unroll
        for(int rg = 0; rg < 2; rg++){
            #pragma unroll
            for(int j = 0; j < 2; j++){
                int cid = cid0 | j;
                int row = cid >> 2, ch = cid & 3;
                const __half* src = (rg ? Bt : A) +
                    (size_t)((rg ? bn : bm) + row) * K + kt * 32 + (ch << 3);
                uint32_t dst = sb + 2u * (uint32_t)(s * 8192 + rg * 4096 +
                               row * 32 + ((ch ^ ((row >> 1) & 3)) << 3));
                CPASYNC16(dst, src);
            }
        }
    };

    const int T = K >> 5;
    prefetch(0, 0);
    asm volatile("cp.async.commit_group;");
    prefetch(1, 1);
    asm volatile("cp.async.commit_group;");

    for(int kt = 0; kt < T; kt++){
        const int s = kt % 3;
        if(kt + 1 < T) asm volatile("cp.async.wait_group 1;");
        else           asm volatile("cp.async.wait_group 0;");
        __syncthreads();                      // data ready + prev compute done
        if(kt + 2 < T){
            prefetch((kt + 2) % 3, kt + 2);
            asm volatile("cp.async.commit_group;");
        }
        const uint32_t stg = sb + 2u * (uint32_t)(s * 8192);
        #pragma unroll
        for(int kk = 0; kk < 2; kk++){
            uint32_t a[2][4];
            #pragma unroll
            for(int mt = 0; mt < 2; mt++){
                int R = wm + mt * 16 + (lane & 15);
                int phys = (kk * 2 + (lane >> 4)) ^ ((R >> 1) & 3);
                LDSM4(a[mt], stg + 2u * (uint32_t)(R * 32 + (phys << 3)));
            }
            #pragma unroll
            for(int ng = 0; ng < 4; ng++){
                int R = wn + ng * 16 + (lane & 7) + ((lane >> 4) << 3);
                int phys = (kk * 2 + ((lane >> 3) & 1)) ^ ((R >> 1) & 3);
                uint32_t b[4];
                LDSM4(b, stg + 2u * (uint32_t)(4096 + R * 32 + (phys << 3)));
                #pragma unroll
                for(int mt = 0; mt < 2; mt++){
                    MMA16816(c[mt][2*ng],   a[mt], b[0], b[1]);
                    MMA16816(c[mt][2*ng+1], a[mt], b[2], b[3]);
                }
            }
        }
    }

    // ---- epilogues ----
    if(EP == 2){
        // qkv projection: warp covers exactly one head (64 cols).
        // col d and d+32 (RoPE partner) are in the same thread (nt, nt+4).
        const int hidx = (bn + wn) >> 6;     // 0..15 q, 16..23 k, 24..31 v
        #pragma unroll
        for(int mt = 0; mt < 2; mt++){
            #pragma unroll
            for(int half = 0; half < 2; half++){
                const int token = bm + wm + mt * 16 + (lane >> 2) + half * 8;
                const int jb = half << 1;
                const int bb = token >> 10, sp = token & (SS - 1);
                __half* dst;
                if(hidx < 16)      dst = qp + (((size_t)bb*HH  + hidx)      * SS + sp) * HDD;
                else if(hidx < 24) dst = kp + (((size_t)bb*HKK + hidx - 16) * SS + sp) * HDD;
                else               dst = vp + (((size_t)bb*HKK + hidx - 24) * SS + sp) * HDD;
                if(hidx >= 24){
                    #pragma unroll
                    for(int nt = 0; nt < 8; nt++){
                        int d = nt * 8 + ((lane & 3) << 1);
                        *(uint32_t*)&dst[d] = f22h(c[mt][nt][jb], c[mt][nt][jb+1]);
                    }
                } else {
                    const float* wn2 = (hidx < 16) ? qw : kw;
                    float ssq = 0.f;
                    #pragma unroll
                    for(int nt = 0; nt < 8; nt++)
                        ssq += c[mt][nt][jb]*c[mt][nt][jb] + c[mt][nt][jb+1]*c[mt][nt][jb+1];
                    ssq += __shfl_xor_sync(~0u, ssq, 1);
                    ssq += __shfl_xor_sync(~0u, ssq, 2);
                    float rn = rsqrtf(ssq * (1.f/64.f) + 1e-6f);
                    float scq = (hidx < 16) ? 0.125f : 1.f;   // fold softmax scale
                    #pragma unroll
                    for(int nt = 0; nt < 4; nt++){
                        float yl[2], yh[2];
                        #pragma unroll
                        for(int e = 0; e < 2; e++){
                            int d = nt * 8 + ((lane & 3) << 1) + e;
                            float x0 = c[mt][nt][jb+e]   * rn * wn2[d];
                            float x1 = c[mt][nt+4][jb+e] * rn * wn2[d+32];
                            float ang = (float)sp * expf(-(float)d * 0.431734704963f);
                            float sn, cs; sincosf(ang, &sn, &cs);
                            yl[e] = (x0 * cs - x1 * sn) * scq;
                            yh[e] = (x1 * cs + x0 * sn) * scq;
                        }
                        int d0 = nt * 8 + ((lane & 3) << 1);
                        *(uint32_t*)&dst[d0]      = f22h(yl[0], yl[1]);
                        *(uint32_t*)&dst[d0+32]   = f22h(yh[0], yh[1]);
                    }
                }
            }
        }
        return;
    }
    #pragma unroll
    for(int mt = 0; mt < 2; mt++)
        #pragma unroll
        for(int nt = 0; nt < 8; nt++){
            int r  = bm + wm + mt * 16 + (lane >> 2);
            int cc = bn + wn + nt * 8 + ((lane & 3) << 1);
            if(EP == 1){
                int j = cc >> 1;
                float g0 = c[mt][nt][0], u0 = c[mt][nt][1];
                float g1 = c[mt][nt][2], u1 = c[mt][nt][3];
                float o0 = g0 / (1.f + expf(-g0)) * u0;
                float o1 = g1 / (1.f + expf(-g1)) * u1;
                Ch[(size_t)r * (N >> 1) + j]       = __float2half_rn(o0);
                Ch[(size_t)(r + 8) * (N >> 1) + j] = __float2half_rn(o1);
            } else {
                float* p0 = C + (size_t)r * N + cc;
                float* p1 = C + (size_t)(r + 8) * N + cc;
                float2 v0 = make_float2(c[mt][nt][0], c[mt][nt][1]);
                float2 v1 = make_float2(c[mt][nt][2], c[mt][nt][3]);
                if(ACC){
                    float2 o = *(const float2*)p0; v0.x += o.x; v0.y += o.y;
                    o = *(const float2*)p1;        v1.x += o.x; v1.y += o.y;
                }
                *(float2*)p0 = v0;
                *(float2*)p1 = v1;
            }
        }
}

// ---------------- transpose + fp16 convert: d[n*nmul+noff][k] = src[k][n] ----
__global__ void transpose_fp16(const float* __restrict__ src,
                               __half* __restrict__ dst, int K, int N,
                               int nmul, int noff){
    __shared__ float t[32][33];
    int k0 = blockIdx.y << 5, n0 = blockIdx.x << 5;
    int x = threadIdx.x, y = threadIdx.y;
    #pragma unroll
    for(int i = 0; i < 32; i += 8) t[y + i][x] = src[(size_t)(k0 + y + i) * N + n0 + x];
    __syncthreads();
    #pragma unroll
    for(int i = 0; i < 32; i += 8)
        dst[((size_t)(n0 + y + i) * nmul + noff) * K + k0 + x] = __float2half_rn(t[x][y + i]);
}

// ---------------- RMSNorm over rows of width DD ------------------------------
template<int HF>
__global__ void rmsnorm_k(const float* __restrict__ x, const float* __restrict__ w,
                          float* __restrict__ out, __half* __restrict__ oh){
    int row = blockIdx.x;
    const float4* xr = (const float4*)(x + (size_t)row * DD);
    float4 v = xr[threadIdx.x];
    float ss = v.x*v.x + v.y*v.y + v.z*v.z + v.w*v.w;
    __shared__ float red[8];
    #pragma unroll
    for(int o = 16; o; o >>= 1) ss += __shfl_xor_sync(~0u, ss, o);
    if((threadIdx.x & 31) == 0) red[threadIdx.x >> 5] = ss;
    __syncthreads();
    if(threadIdx.x < 8){
        float t = red[threadIdx.x];
        #pragma unroll
        for(int o = 4; o; o >>= 1) t += __shfl_xor_sync(0xff, t, o);
        if(threadIdx.x == 0) red[0] = rsqrtf(t / (float)DD + 1e-6f);
    }
    __syncthreads();
    float r = red[0];
    float4 wv = ((const float4*)w)[threadIdx.x];
    float4 o4 = make_float4(v.x*r*wv.x, v.y*r*wv.y, v.z*r*wv.z, v.w*r*wv.w);
    if(HF){
        *(uint2*)&oh[(size_t)row * DD + (threadIdx.x << 2)] = pack4h(o4);
    } else {
        ((float4*)(out + (size_t)row * DD))[threadIdx.x] = o4;
    }
}

// ---------------- tensor-core flash attention --------------------------------
__global__ void __launch_bounds__(128) attn_mma(const int* __restrict__ amask,
                                                int win, __half* __restrict__ Ch){
    __shared__ __align__(16) __half Qs[4096];
    __shared__ __align__(16) __half Ks[2][4096];
    __shared__ __align__(16) __half Vs[2][4096];
    __shared__ int msk[64];
    const int b = blockIdx.z, h = blockIdx.y, q0 = blockIdx.x << 6;
    const int kvh = h >> 1;
    const int tid = threadIdx.x, lane = tid & 31, w = tid >> 5;
    const uint32_t sq = smem_u32(Qs);
    const uint32_t sk = smem_u32(Ks);
    const uint32_t sv = smem_u32(Vs);

    const __half* Qg = g_qh + (((size_t)b * HH + h) * SS + q0) * HDD;
    const __half* Kg = g_kh + ((size_t)b * HKK + kvh) * SS * HDD;
    const __half* Vg = g_vh + ((size_t)b * HKK + kvh) * SS * HDD;

    #pragma unroll
    for(int i = 0; i < 4; i++){
        int cid = tid + (i << 7);
        int row = cid >> 3, ch = cid & 7;
        CPASYNC16(sq + (uint32_t)(row * 128 + ((ch ^ (row & 7)) << 4)),
                  Qg + row * HDD + ch * 8);
    }
    const bool full = (win >= SS);
    int kbeg = 0, kend = SS;
    if(!full){ kbeg = max(0, q0 - win) & ~63; kend = min(SS, q0 + 63 + win + 1); }

    auto ldtile = [&](int s, int kt){
        #pragma unroll
        for(int i = 0; i < 4; i++){
            int cid = tid + (i << 7);
            int row = cid >> 3, ch = cid & 7;
            uint32_t off = (uint32_t)((s << 13) + row * 128 + ((ch ^ (row & 7)) << 4));
            CPASYNC16(sk + off, Kg + (size_t)(kt + row) * HDD + ch * 8);
            CPASYNC16(sv + off, Vg + (size_t)(kt + row) * HDD + ch * 8);
        }
    };
    ldtile(0, kbeg);
    asm volatile("cp.async.commit_group;");

    float o[8][4];
    #pragma unroll
    for(int i = 0; i < 8; i++){ o[i][0]=0.f; o[i][1]=0.f; o[i][2]=0.f; o[i][3]=0.f; }
    float m0 = -1e30f, m1 = -1e30f, l0 = 0.f, l1 = 0.f;
    uint32_t qa[4][4];

    const int nTiles = (kend - kbeg + 63) >> 6;
    for(int it = 0; it < nTiles; it++){
        const int kt = kbeg + (it << 6);
        const int s = it & 1;
        if(it + 1 < nTiles){
            ldtile(s ^ 1, kt + 64);
            asm volatile("cp.async.commit_group;");
            asm volatile("cp.async.wait_group 1;");
        } else {
            asm volatile("cp.async.wait_group 0;");
        }
        if(tid < 64) msk[tid] = amask[b * SS + kt + tid];
        __syncthreads();
        if(it == 0){
            #pragma unroll
            for(int kk = 0; kk < 4; kk++){
                int R = (w << 4) + (lane & 15);
                int ch = (kk << 1) + (lane >> 4);
                LDSM4(qa[kk], sq + (uint32_t)(R * 128 + ((ch ^ (R & 7)) << 4)));
            }
        }
        float sc[8][4];
        #pragma unroll
        for(int i = 0; i < 8; i++){ sc[i][0]=0.f; sc[i][1]=0.f; sc[i][2]=0.f; sc[i][3]=0.f; }
        const uint32_t skb = sk + (uint32_t)(s << 13);
        #pragma unroll
        for(int kk = 0; kk < 4; kk++){
            #pragma unroll
            for(int ng = 0; ng < 4; ng++){
                int R = (ng << 4) + (lane & 7) + ((lane >> 4) << 3);
                int ch = (kk << 1) + ((lane >> 3) & 1);
                uint32_t bk[4];
                LDSM4(bk, skb + (uint32_t)(R * 128 + ((ch ^ (R & 7)) << 4)));
                MMA16816(sc[2*ng],   qa[kk], bk[0], bk[1]);
                MMA16816(sc[2*ng+1], qa[kk], bk[2], bk[3]);
            }
        }
        const int qr0 = q0 + (w << 4) + (lane >> 2), qr1 = qr0 + 8;
        float mx0 = -1e30f, mx1 = -1e30f;
        #pragma unroll
        for(int nt = 0; nt < 8; nt++){
            int c0 = (nt << 3) + ((lane & 3) << 1);
            int j0 = kt + c0, j1 = j0 + 1;
            bool k0 = msk[c0] > 0, k1 = msk[c0 + 1] > 0;
            if(!(k0 && (full || abs(qr0 - j0) <= win))) sc[nt][0] = -1e30f;
            if(!(k1 && (full || abs(qr0 - j1) <= win))) sc[nt][1] = -1e30f;
            if(!(k0 && (full || abs(qr1 - j0) <= win))) sc[nt][2] = -1e30f;
            if(!(k1 && (full || abs(qr1 - j1) <= win))) sc[nt][3] = -1e30f;
            mx0 = fmaxf(mx0, fmaxf(sc[nt][0], sc[nt][1]));
            mx1 = fmaxf(mx1, fmaxf(sc[nt][2], sc[nt][3]));
        }
        mx0 = fmaxf(mx0, __shfl_xor_sync(~0u, mx0, 1));
        mx0 = fmaxf(mx0, __shfl_xor_sync(~0u, mx0, 2));
        mx1 = fmaxf(mx1, __shfl_xor_sync(~0u, mx1, 1));
        mx1 = fmaxf(mx1, __shfl_xor_sync(~0u, mx1, 2));
        float mn0 = fmaxf(m0, mx0), mn1 = fmaxf(m1, mx1);
        float cor0 = expf(m0 - mn0), cor1 = expf(m1 - mn1);
        float s0 = 0.f, s1 = 0.f;
        #pragma unroll
        for(int nt = 0; nt < 8; nt++){
            sc[nt][0] = (sc[nt][0] > -1e29f) ? expf(sc[nt][0] - mn0) : 0.f;
            sc[nt][1] = (sc[nt][1] > -1e29f) ? expf(sc[nt][1] - mn0) : 0.f;
            sc[nt][2] = (sc[nt][2] > -1e29f) ? expf(sc[nt][2] - mn1) : 0.f;
            sc[nt][3] = (sc[nt][3] > -1e29f) ? expf(sc[nt][3] - mn1) : 0.f;
            s0 += sc[nt][0] + sc[nt][1];
            s1 += sc[nt][2] + sc[nt][3];
        }
        s0 += __shfl_xor_sync(~0u, s0, 1); s0 += __shfl_xor_sync(~0u, s0, 2);
        s1 += __shfl_xor_sync(~0u, s1, 1); s1 += __shfl_xor_sync(~0u, s1, 2);
        l0 = l0 * cor0 + s0;  l1 = l1 * cor1 + s1;
        m0 = mn0;  m1 = mn1;
        #pragma unroll
        for(int nt = 0; nt < 8; nt++){
            o[nt][0] *= cor0; o[nt][1] *= cor0;
            o[nt][2] *= cor1; o[nt][3] *= cor1;
        }
        const uint32_t svb = sv + (uint32_t)(s << 13);
        #pragma unroll
        for(int kk = 0; kk < 4; kk++){
            uint32_t pa[4];
            pa[0] = f22h(sc[2*kk][0],   sc[2*kk][1]);
            pa[1] = f22h(sc[2*kk][2],   sc[2*kk][3]);
            pa[2] = f22h(sc[2*kk+1][0], sc[2*kk+1][1]);
            pa[3] = f22h(sc[2*kk+1][2], sc[2*kk+1][3]);
            #pragma unroll
            for(int hg = 0; hg < 4; hg++){
                int R = (kk << 4) + (((lane >> 3) & 1) << 3) + (lane & 7);
                int ch = (hg << 1) + (lane >> 4);
                uint32_t bv[4];
                LDSM4T(bv, svb + (uint32_t)(R * 128 + ((ch ^ (R & 7)) << 4)));
                MMA16816(o[2*hg],   pa, bv[0], bv[1]);
                MMA16816(o[2*hg+1], pa, bv[2], bv[3]);
            }
        }
        __syncthreads();
    }
    float i0 = (l0 > 0.f) ? 1.f / l0 : 0.f;
    float i1 = (l1 > 0.f) ? 1.f / l1 : 0.f;
    const int row0 = (b << 10) + q0 + (w << 4) + (lane >> 2);
    const int row1 = row0 + 8;
    #pragma unroll
    for(int nt = 0; nt < 8; nt++){
        int col = (h << 6) + (nt << 3) + ((lane & 3) << 1);
        *(uint32_t*)&Ch[(size_t)row0 * DD + col] = f22h(o[nt][0] * i0, o[nt][1] * i0);
        *(uint32_t*)&Ch[(size_t)row1 * DD + col] = f22h(o[nt][2] * i1, o[nt][3] * i1);
    }
}

// ---------------- driver -----------------------------------------------------
extern "C" void kernel_launch(void* const* d_in, const int* in_sizes, int n_in,
                              void* d_out, int out_size){
    const float* emb = (const float*)d_in[0];
    const float* wq  = (const float*)d_in[1];
    const float* wk  = (const float*)d_in[2];
    const float* wv  = (const float*)d_in[3];
    const float* wo  = (const float*)d_in[4];
    const float* qnw = (const float*)d_in[5];
    const float* knw = (const float*)d_in[6];
    const float* ln1 = (const float*)d_in[7];
    const float* ln2 = (const float*)d_in[8];
    const float* wg  = (const float*)d_in[9];
    const float* wu  = (const float*)d_in[10];
    const float* wd  = (const float*)d_in[11];
    const float* nw  = (const float*)d_in[12];
    const int*   am  = (const int*)d_in[13];

    float *p_h;
    __half *p_wt, *p_nh, *p_ch, *p_ah, *p_qh, *p_kh, *p_vh;
    cudaGetSymbolAddress((void**)&p_h,  g_h);
    cudaGetSymbolAddress((void**)&p_wt, g_wt);
    cudaGetSymbolAddress((void**)&p_nh, g_nh);
    cudaGetSymbolAddress((void**)&p_ch, g_ch);
    cudaGetSymbolAddress((void**)&p_ah, g_ah);
    cudaGetSymbolAddress((void**)&p_qh, g_qh);
    cudaGetSymbolAddress((void**)&p_kh, g_kh);
    cudaGetSymbolAddress((void**)&p_vh, g_vh);

    cudaMemcpyAsync(p_h, emb, sizeof(float) * (size_t)NTOK * DD,
                    cudaMemcpyDeviceToDevice);

    dim3 tb(32, 8);
    for(int l = 0; l < LL; l++){
        __half* wb = p_wt + (size_t)l * W1_LAYER;
        transpose_fp16<<<dim3(32, 32), tb>>>(wq + (size_t)l*1024*1024,
            wb + W1_QKV,             1024, 1024, 1, 0);
        transpose_fp16<<<dim3(16, 32), tb>>>(wk + (size_t)l*1024*512,
            wb + W1_QKV + 1048576,   1024, 512, 1, 0);
        transpose_fp16<<<dim3(16, 32), tb>>>(wv + (size_t)l*1024*512,
            wb + W1_QKV + 1572864,   1024, 512, 1, 0);
        transpose_fp16<<<dim3(32, 32), tb>>>(wo + (size_t)l*1024*1024,
            wb + W1_WO,              1024, 1024, 1, 0);
        transpose_fp16<<<dim3(96, 32), tb>>>(wg + (size_t)l*1024*FFF,
            wb + W1_GU,              1024, 3072, 2, 0);
        transpose_fp16<<<dim3(96, 32), tb>>>(wu + (size_t)l*1024*FFF,
            wb + W1_GU,              1024, 3072, 2, 1);
        transpose_fp16<<<dim3(32, 96), tb>>>(wd + (size_t)l*FFF*1024,
            wb + W1_DN,              3072, 1024, 1, 0);
    }

    for(int l = 0; l < LL; l++){
        __half* wb = p_wt + (size_t)l * W1_LAYER;
        rmsnorm_k<1><<<NTOK, 256>>>(p_h, ln1 + (size_t)l * DD, nullptr, p_nh);
        gemm_mma<0,2><<<dim3(16, 32), 256>>>(p_nh, wb + W1_QKV, nullptr, nullptr,
            1024, 2048, qnw + (size_t)l * HDD, knw + (size_t)l * HDD,
            p_qh, p_kh, p_vh);
        attn_mma<<<dim3(SS / 64, HH, Bb), 128>>>(am, (l % 2 == 0) ? SS : WIN_, p_ch);
        gemm_mma<1,0><<<dim3(8, 32), 256>>>(p_ch, wb + W1_WO, p_h, nullptr,
            1024, 1024, nullptr, nullptr, nullptr, nullptr, nullptr);
        rmsnorm_k<1><<<NTOK, 256>>>(p_h, ln2 + (size_t)l * DD, nullptr, p_nh);
        gemm_mma<0,1><<<dim3(48, 32), 256>>>(p_nh, wb + W1_GU, nullptr, p_ah,
            1024, 6144, nullptr, nullptr, nullptr, nullptr, nullptr);
        gemm_mma<1,0><<<dim3(8, 32), 256>>>(p_ah, wb + W1_DN, p_h, nullptr,
            3072, 1024, nullptr, nullptr, nullptr, nullptr, nullptr);
    }
    rmsnorm_k<0><<<NTOK, 256>>>(p_h, nw, (float*)d_out, nullptr);
}